// round 12
// baseline (speedup 1.0000x reference)
#include <cuda_runtime.h>
#include <cstdint>

// Problem constants
static constexpr int Lc  = 32;
static constexpr int Kc  = 4;
static constexpr int Dc  = 1024;
static constexpr int QOc = 1024;
static constexpr int KVc = 256;
static constexpr int FFc = 2816;

typedef unsigned long long ull;

// Per-warp smem: 3 buffers x (64 rows x 16 w-cols + 12 vecs x 16 c-cols).
static constexpr int WB_FL = 64 * 16 + 12 * 16;    // 1216 floats per buffer
static constexpr int PW_FL = 3 * WB_FL;            // 3648 floats per warp
static constexpr int SMEM_BYTES = 4 * PW_FL * 4;   // 58368 B per 4-warp CTA

// ---------------- f32x2 packed FMA (sm_103a) ----------------
__device__ __forceinline__ void fma2(ull& acc, ull a, ull b) {
    asm("fma.rn.f32x2 %0, %1, %2, %0;" : "+l"(acc) : "l"(a), "l"(b));
}
__device__ __forceinline__ float hsum2(ull v) {
    return __uint_as_float((uint32_t)v) + __uint_as_float((uint32_t)(v >> 32));
}

// ---------------- cp.async helpers ----------------
__device__ __forceinline__ void cp_async16(uint32_t saddr, const void* gptr) {
    asm volatile("cp.async.cg.shared.global [%0], [%1], 16;" :: "r"(saddr), "l"(gptr));
}
__device__ __forceinline__ void cp_commit() {
    asm volatile("cp.async.commit_group;");
}
template<int N>
__device__ __forceinline__ void cp_wait() {
    asm volatile("cp.async.wait_group %0;" :: "n"(N));
}

// =====================================================================
// run_unit: warp-private streaming GEMV, 2 rows per lane (64-row unit).
// Tiles of 16 cols staged via cp.async into a per-warp triple-buffered
// slab; weights read back with a swizzled LDS.128 (lane reads rows lane
// and lane+32); cursed quads broadcast from smem. Cursed LDS amortized
// over 64 rows. acc per lane: M vecs x 2 rows. __syncwarp only.
// =====================================================================
template<int M, int I>
__device__ __forceinline__ void run_unit(const float* __restrict__ Wg,  // +row0*I
                                         const float* __restrict__ Cg,  // vec v at +v*I
                                         float* __restrict__ swarp,
                                         ull* __restrict__ acc_a,       // rows lane
                                         ull* __restrict__ acc_b,       // rows lane+32
                                         int lane)
{
    constexpr int NT = I / 16;
    const uint32_t sb = (uint32_t)__cvta_generic_to_shared(swarp);

    auto stage = [&](int ct, int buf) {
        const int c0 = ct * 16;
        const uint32_t bb = sb + (uint32_t)buf * (WB_FL * 4);
        // Weights: 64 rows x 64 B = 256 16B-transfers, 8 per lane. Swizzled dst.
#pragma unroll
        for (int i = 0; i < 8; ++i) {
            const int t    = i * 32 + lane;
            const int row  = t >> 2;
            const int quad = t & 3;
            const uint32_t dst = bb + (uint32_t)(row * 64 + ((quad ^ ((row >> 1) & 3)) * 16));
            cp_async16(dst, Wg + (size_t)row * I + c0 + quad * 4);
        }
        // Cursed: M x 16 floats = M*4 transfers (<= 48).
#pragma unroll
        for (int i = 0; i < (M * 4 + 31) / 32; ++i) {
            const int t = i * 32 + lane;
            if (t < M * 4) {
                const int v = t >> 2, cq = t & 3;
                cp_async16(bb + 4096u + (uint32_t)(v * 64 + cq * 16),
                           Cg + (size_t)v * I + c0 + cq * 4);
            }
        }
    };

    stage(0, 0); cp_commit();
    stage(1, 1); cp_commit();

    const int swz = (lane >> 1) & 3;      // same for row lane and lane+32
    int buf = 0;
    for (int ct = 0; ct < NT; ++ct) {
        cp_wait<1>();
        __syncwarp();
        // Prefetch tile ct+2 into the buffer tile ct-1 just vacated.
        if (ct + 2 < NT) stage(ct + 2, (buf == 0) ? 2 : buf - 1);
        cp_commit();

        const float* wb    = swarp + buf * WB_FL;
        const float* wrowA = wb + lane * 16;
        const float* wrowB = wb + (lane + 32) * 16;
        const float* cb    = wb + 1024;
#pragma unroll
        for (int q = 0; q < 4; ++q) {
            const double2 wa = *reinterpret_cast<const double2*>(wrowA + ((q ^ swz) * 4));
            const double2 wbd = *reinterpret_cast<const double2*>(wrowB + ((q ^ swz) * 4));
            const ull wa01 = __double_as_longlong(wa.x);
            const ull wa23 = __double_as_longlong(wa.y);
            const ull wb01 = __double_as_longlong(wbd.x);
            const ull wb23 = __double_as_longlong(wbd.y);
#pragma unroll
            for (int v = 0; v < M; ++v) {
                const double2 cd = *reinterpret_cast<const double2*>(cb + v * 16 + q * 4);
                const ull c01 = __double_as_longlong(cd.x);
                const ull c23 = __double_as_longlong(cd.y);
                fma2(acc_a[v], wa01, c01);
                fma2(acc_a[v], wa23, c23);
                fma2(acc_b[v], wb01, c01);
                fma2(acc_b[v], wb23, c23);
            }
        }
        buf = (buf == 2) ? 0 : buf + 1;
    }
}

// =====================================================================
// Fused kernel, 128-thr blocks (4 warps), 3 CTAs/SM.
// Proj blocks [0,640): global warp g = b*4 + w in [0,2560);
//   stratum = g % 5 (0 MLP, 1 Q, 2 O, 3 K, 4 V), idx = g/5 in [0,512):
//   l = idx>>4, 64-row chunk rc = idx&15.  (Strata interleaved for balance.)
// Copy blocks [640,752): residual -> out (s=0 rows), 2048 float4 each.
// Output row(l,m,k) = l*56 + m*8 + 4 + k (projected side s=1).
// =====================================================================
extern "C" __global__ void __launch_bounds__(128, 3)
both_sides_fused(const float* __restrict__ residual,
                 const float* __restrict__ cq, const float* __restrict__ ck,
                 const float* __restrict__ cv, const float* __restrict__ co,
                 const float* __restrict__ cm,
                 const float* __restrict__ Wq, const float* __restrict__ Wk,
                 const float* __restrict__ Wv, const float* __restrict__ Wo,
                 const float* __restrict__ Wd,
                 float* __restrict__ out)
{
    extern __shared__ __align__(16) float smem[];

    const int b = blockIdx.x;
    if (b >= 640) {                       // residual copy
        const float4* r4 = reinterpret_cast<const float4*>(residual);
        float4* o4 = reinterpret_cast<float4*>(out);
        const int i0 = (b - 640) * 2048 + (int)threadIdx.x;
#pragma unroll
        for (int j = 0; j < 16; ++j) {
            const int i = i0 + j * 128;   // < 229376
            const int chunk  = i >> 10;   // (l,m): 1024 float4 per chunk
            const int within = i & 1023;
            o4[(size_t)chunk * 2048 + within] = r4[i];
        }
        return;
    }

    const int lane = threadIdx.x & 31;
    const int warp = threadIdx.x >> 5;
    const int g    = b * 4 + warp;        // [0, 2560)
    const int stratum = g % 5;
    const int idx     = g / 5;            // [0, 512)
    const int l    = idx >> 4;
    const int rc   = idx & 15;
    const int row0 = rc * 64;
    float* swarp = smem + warp * PW_FL;

    if (stratum == 0) {                                // MLP: 12 vecs
        ull aa[12], ab[12];
#pragma unroll
        for (int v = 0; v < 12; ++v) { aa[v] = 0ull; ab[v] = 0ull; }
        run_unit<12, FFc>(Wd + ((size_t)l * Dc + row0) * FFc,
                          cm + (size_t)l * 12 * FFc, swarp, aa, ab, lane);
#pragma unroll
        for (int v = 0; v < 12; ++v) {
            const int mi = v >> 2;                     // 0,1,2 -> gate,up,down
            const int m  = (mi == 2) ? 6 : (3 + mi);   // gate=3, up=4, down=6
            const int k  = v & 3;
            const size_t orow = (size_t)(l * 56 + m * 8 + 4 + k) * 1024;
            out[orow + row0 + lane]      = hsum2(aa[v]);
            out[orow + row0 + 32 + lane] = hsum2(ab[v]);
        }
    } else {                                           // Q / O / K / V
        const float* W; const float* C; int m, I;
        switch (stratum) {
            case 1: W = Wq; C = cq; m = 0; I = QOc; break;
            case 2: W = Wo; C = co; m = 5; I = QOc; break;
            case 3: W = Wk; C = ck; m = 1; I = KVc; break;
            default: W = Wv; C = cv; m = 2; I = KVc; break;
        }
        ull aa[4], ab[4];
#pragma unroll
        for (int v = 0; v < 4; ++v) { aa[v] = 0ull; ab[v] = 0ull; }
        if (I == QOc)
            run_unit<4, QOc>(W + ((size_t)l * Dc + row0) * QOc,
                             C + (size_t)l * 4 * QOc, swarp, aa, ab, lane);
        else
            run_unit<4, KVc>(W + ((size_t)l * Dc + row0) * KVc,
                             C + (size_t)l * 4 * KVc, swarp, aa, ab, lane);
#pragma unroll
        for (int v = 0; v < 4; ++v) {
            const size_t orow = (size_t)(l * 56 + m * 8 + 4 + v) * 1024;
            out[orow + row0 + lane]      = hsum2(aa[v]);
            out[orow + row0 + 32 + lane] = hsum2(ab[v]);
        }
    }
}

extern "C" void kernel_launch(void* const* d_in, const int* in_sizes, int n_in,
                              void* d_out, int out_size)
{
    const float* residual = (const float*)d_in[0];
    const float* cq       = (const float*)d_in[1];
    const float* ck       = (const float*)d_in[2];
    const float* cv       = (const float*)d_in[3];
    const float* co       = (const float*)d_in[4];
    const float* cm       = (const float*)d_in[5];
    const float* Wq       = (const float*)d_in[6];
    const float* Wk       = (const float*)d_in[7];
    const float* Wv       = (const float*)d_in[8];
    const float* Wo       = (const float*)d_in[9];
    const float* Wd       = (const float*)d_in[10];
    float* out            = (float*)d_out;

    static bool attr_set = false;
    if (!attr_set) {
        cudaFuncSetAttribute(both_sides_fused,
                             cudaFuncAttributeMaxDynamicSharedMemorySize,
                             SMEM_BYTES);
        attr_set = true;
    }

    both_sides_fused<<<752, 128, SMEM_BYTES>>>(residual, cq, ck, cv, co, cm,
                                               Wq, Wk, Wv, Wo, Wd, out);
}

// round 13
// speedup vs baseline: 1.5198x; 1.5198x over previous
#include <cuda_runtime.h>
#include <cstdint>

// Problem constants
static constexpr int Lc  = 32;
static constexpr int Kc  = 4;
static constexpr int Dc  = 1024;
static constexpr int QOc = 1024;
static constexpr int KVc = 256;
static constexpr int FFc = 2816;

typedef unsigned long long ull;

// Per-warp smem buffer: 64 weight rows x 12-float padded stride (8 used)
// + 12 cursed vecs x 8 floats. 864 floats = 3456 B; 3 buffers per warp.
static constexpr int WROW_F  = 12;                 // padded row stride (floats)
static constexpr int WB_FL   = 64 * WROW_F + 12 * 8;   // 864
static constexpr int PW_FL   = 3 * WB_FL;              // 2592
static constexpr int SMEM_BYTES = 8 * PW_FL * 4;       // 82944 B per CTA

// Scratch partials (device globals).
__device__ float scratchM[2048 * 12 * 64];   // [unit][vec][row]
__device__ float scratchQ[1024 * 4 * 64];
__device__ float scratchO[1024 * 4 * 64];

// ---------------- f32x2 packed FMA (sm_103a) ----------------
__device__ __forceinline__ void fma2(ull& acc, ull a, ull b) {
    asm("fma.rn.f32x2 %0, %1, %2, %0;" : "+l"(acc) : "l"(a), "l"(b));
}
__device__ __forceinline__ float hsum2(ull v) {
    return __uint_as_float((uint32_t)v) + __uint_as_float((uint32_t)(v >> 32));
}

// ---------------- cp.async helpers ----------------
__device__ __forceinline__ void cp_async16(uint32_t saddr, const void* gptr) {
    asm volatile("cp.async.cg.shared.global [%0], [%1], 16;" :: "r"(saddr), "l"(gptr));
}
__device__ __forceinline__ void cp_commit() {
    asm volatile("cp.async.commit_group;");
}
template<int N>
__device__ __forceinline__ void cp_wait() {
    asm volatile("cp.async.wait_group %0;" :: "n"(N));
}

// =====================================================================
// run_unit: warp-private streaming GEMV; 64 rows (2 per lane: lane,
// lane+32) x NT*8 cols, M vecs. 8-col tiles cp.async'd into a per-warp
// triple-buffered slab (48B-padded rows => conflict-free LDS.128 on the
// 3r-mod-8 permutation). Cursed quads broadcast from smem. acc[M] x 2
// per lane. __syncwarp only; prefetch distance 2.
// =====================================================================
template<int M, int I, int NT>
__device__ __forceinline__ void run_unit(const float* __restrict__ Wg, // +row0*I+c0
                                         const float* __restrict__ Cg, // +v*I+c0
                                         float* __restrict__ swarp,
                                         ull* __restrict__ accA,
                                         ull* __restrict__ accB,
                                         int lane)
{
    const uint32_t sb = (uint32_t)__cvta_generic_to_shared(swarp);

    // Per-lane staging constants.
    //  w: 128 transfers (64 rows x 2 quads), lane's share i<4: t=i*32+lane,
    //     row=t>>1, quad=t&1.
    const float* wsrc[4];
    uint32_t     wdst[4];
#pragma unroll
    for (int i = 0; i < 4; ++i) {
        const int t = i * 32 + lane;
        const int r = t >> 1, q = t & 1;
        wsrc[i] = Wg + (size_t)r * I + q * 4;
        wdst[i] = (uint32_t)(r * (WROW_F * 4) + q * 16);
    }
    //  c: 2*M transfers, lane<2*M: v=lane>>1, q=lane&1.
    const int cv = lane >> 1, cq = lane & 1;
    const float* csrc = Cg + (size_t)cv * I + cq * 4;
    const uint32_t cdst = (uint32_t)(64 * WROW_F * 4 + cv * 32 + cq * 16);
    const bool cact = lane < 2 * M;

    auto stage = [&](int ct, int buf) {
        const uint32_t bb = sb + (uint32_t)buf * (WB_FL * 4);
        const int co = ct * 8;
#pragma unroll
        for (int i = 0; i < 4; ++i)
            cp_async16(bb + wdst[i], wsrc[i] + co);
        if (cact) cp_async16(bb + cdst, csrc + co);
    };

    stage(0, 0); cp_commit();
    stage(1, 1); cp_commit();

    int buf = 0;
    for (int ct = 0; ct < NT; ++ct) {
        cp_wait<1>();
        __syncwarp();
        if (ct + 2 < NT) stage(ct + 2, (buf == 0) ? 2 : buf - 1);
        cp_commit();

        const float* wb    = swarp + buf * WB_FL;
        const float* wrowA = wb + lane * WROW_F;
        const float* wrowB = wb + (lane + 32) * WROW_F;
        const float* cb    = wb + 64 * WROW_F;

        const double2 a0 = *reinterpret_cast<const double2*>(wrowA);
        const double2 a1 = *reinterpret_cast<const double2*>(wrowA + 4);
        const double2 b0 = *reinterpret_cast<const double2*>(wrowB);
        const double2 b1 = *reinterpret_cast<const double2*>(wrowB + 4);
        const ull wa[4] = { __double_as_longlong(a0.x), __double_as_longlong(a0.y),
                            __double_as_longlong(a1.x), __double_as_longlong(a1.y) };
        const ull wbv[4] = { __double_as_longlong(b0.x), __double_as_longlong(b0.y),
                             __double_as_longlong(b1.x), __double_as_longlong(b1.y) };

#pragma unroll
        for (int v = 0; v < M; ++v) {
            const double2 c0d = *reinterpret_cast<const double2*>(cb + v * 8);
            const double2 c1d = *reinterpret_cast<const double2*>(cb + v * 8 + 4);
            const ull c0 = __double_as_longlong(c0d.x), c1 = __double_as_longlong(c0d.y);
            const ull c2 = __double_as_longlong(c1d.x), c3 = __double_as_longlong(c1d.y);
            fma2(accA[v], wa[0], c0); fma2(accA[v], wa[1], c1);
            fma2(accA[v], wa[2], c2); fma2(accA[v], wa[3], c3);
            fma2(accB[v], wbv[0], c0); fma2(accB[v], wbv[1], c1);
            fma2(accB[v], wbv[2], c2); fma2(accB[v], wbv[3], c3);
        }
        buf = (buf == 2) ? 0 : buf + 1;
    }
}

// =====================================================================
// Kernel A: 640 blocks x 256 thr (8 warps), unit u = b*8 + warp:
//   [0,2048)    MLP: cs(4 x 704-col slice), rc(16 x 64 rows), l(32)
//   [2048,4096) Q/O: cs(2 x 512-col slice)
//   [4096,5120) K/V: full 256 cols, direct to out
// =====================================================================
extern "C" __global__ void __launch_bounds__(256, 2)
proj_partials(const float* __restrict__ cq, const float* __restrict__ ck,
              const float* __restrict__ cv, const float* __restrict__ co,
              const float* __restrict__ cm,
              const float* __restrict__ Wq, const float* __restrict__ Wk,
              const float* __restrict__ Wv, const float* __restrict__ Wo,
              const float* __restrict__ Wd,
              float* __restrict__ out)
{
    extern __shared__ __align__(16) float smem[];
    const int lane = threadIdx.x & 31;
    const int warp = threadIdx.x >> 5;
    const int u    = blockIdx.x * 8 + warp;
    float* swarp = smem + warp * PW_FL;

    if (u < 2048) {                                   // MLP
        const int cs = u & 3, rc = (u >> 2) & 15, l = u >> 6;
        const int row0 = rc * 64, c0 = cs * 704;
        ull aa[12], ab[12];
#pragma unroll
        for (int v = 0; v < 12; ++v) { aa[v] = 0ull; ab[v] = 0ull; }
        run_unit<12, FFc, 88>(Wd + ((size_t)l * Dc + row0) * FFc + c0,
                              cm + (size_t)l * 12 * FFc + c0, swarp, aa, ab, lane);
        float* sp = scratchM + (size_t)u * 12 * 64;
#pragma unroll
        for (int v = 0; v < 12; ++v) {
            sp[v * 64 + lane]      = hsum2(aa[v]);
            sp[v * 64 + 32 + lane] = hsum2(ab[v]);
        }
    } else if (u < 4096) {                            // Q / O
        int t = u - 2048;
        const bool isO = t >= 1024; if (isO) t -= 1024;
        const int cs = t & 1, rc = (t >> 1) & 15, l = t >> 5;
        const int row0 = rc * 64, c0 = cs * 512;
        const float* W = isO ? Wo : Wq;
        const float* C = isO ? co : cq;
        ull aa[4], ab[4];
#pragma unroll
        for (int v = 0; v < 4; ++v) { aa[v] = 0ull; ab[v] = 0ull; }
        run_unit<4, QOc, 64>(W + ((size_t)l * Dc + row0) * QOc + c0,
                             C + (size_t)l * 4 * QOc + c0, swarp, aa, ab, lane);
        float* sp = (isO ? scratchO : scratchQ) + (size_t)t * 4 * 64;
#pragma unroll
        for (int v = 0; v < 4; ++v) {
            sp[v * 64 + lane]      = hsum2(aa[v]);
            sp[v * 64 + 32 + lane] = hsum2(ab[v]);
        }
    } else {                                          // K / V -> direct out
        int t = u - 4096;
        const bool isV = t >= 512; if (isV) t -= 512;
        const int rc = t & 15, l = t >> 4;
        const int row0 = rc * 64;
        const float* W = isV ? Wv : Wk;
        const float* C = isV ? cv : ck;
        const int m = isV ? 2 : 1;
        ull aa[4], ab[4];
#pragma unroll
        for (int v = 0; v < 4; ++v) { aa[v] = 0ull; ab[v] = 0ull; }
        run_unit<4, KVc, 32>(W + ((size_t)l * Dc + row0) * KVc,
                             C + (size_t)l * 4 * KVc, swarp, aa, ab, lane);
#pragma unroll
        for (int v = 0; v < 4; ++v) {
            const size_t orow = (size_t)(l * 56 + m * 8 + 4 + v) * 1024;
            out[orow + row0 + lane]      = hsum2(aa[v]);
            out[orow + row0 + 32 + lane] = hsum2(ab[v]);
        }
    }
}

// =====================================================================
// Kernel B: sum slice partials, write outputs, residual copy.
//   [0,393216)        MLP (4 partials)
//   [393216,524288)   Q (2 partials)
//   [524288,655360)   O (2 partials)
//   [655360,884736)   residual copy
// =====================================================================
extern "C" __global__ void __launch_bounds__(256)
reduce_out(const float* __restrict__ residual, float* __restrict__ out)
{
    const int x = blockIdx.x * 256 + threadIdx.x;

    if (x < 393216) {                       // MLP
        const int d = x & 1023;
        int t = x >> 10;
        const int v = t % 12, l = t / 12;
        const int rc = d >> 6, wi = d & 63;
        const float* p = scratchM + ((size_t)((l * 16 + rc) * 4) * 12 + v) * 64 + wi;
        float s = 0.f;
#pragma unroll
        for (int cs = 0; cs < 4; ++cs) s += p[(size_t)cs * 12 * 64];
        const int mi = v >> 2;
        const int m  = (mi == 2) ? 6 : (3 + mi);
        const int k  = v & 3;
        out[(size_t)(l * 56 + m * 8 + 4 + k) * 1024 + d] = s;
    } else if (x < 524288) {                // Q (m=0)
        const int y = x - 393216;
        const int d = y & 1023;
        int t = y >> 10;
        const int k = t & 3, l = t >> 2;
        const int rc = d >> 6, wi = d & 63;
        const float* p = scratchQ + ((size_t)((l * 16 + rc) * 2) * 4 + k) * 64 + wi;
        const float s = p[0] + p[4 * 64];
        out[(size_t)(l * 56 + 0 * 8 + 4 + k) * 1024 + d] = s;
    } else if (x < 655360) {                // O (m=5)
        const int y = x - 524288;
        const int d = y & 1023;
        int t = y >> 10;
        const int k = t & 3, l = t >> 2;
        const int rc = d >> 6, wi = d & 63;
        const float* p = scratchO + ((size_t)((l * 16 + rc) * 2) * 4 + k) * 64 + wi;
        const float s = p[0] + p[4 * 64];
        out[(size_t)(l * 56 + 5 * 8 + 4 + k) * 1024 + d] = s;
    } else {                                // residual copy (s=0 rows)
        const int i = x - 655360;           // < 229376 float4
        const float4* r4 = reinterpret_cast<const float4*>(residual);
        float4* o4 = reinterpret_cast<float4*>(out);
        const int chunk  = i >> 10;         // (l,m): 1024 float4 per chunk
        const int within = i & 1023;
        o4[(size_t)chunk * 2048 + within] = r4[i];
    }
}

extern "C" void kernel_launch(void* const* d_in, const int* in_sizes, int n_in,
                              void* d_out, int out_size)
{
    const float* residual = (const float*)d_in[0];
    const float* cq       = (const float*)d_in[1];
    const float* ck       = (const float*)d_in[2];
    const float* cv       = (const float*)d_in[3];
    const float* co       = (const float*)d_in[4];
    const float* cm       = (const float*)d_in[5];
    const float* Wq       = (const float*)d_in[6];
    const float* Wk       = (const float*)d_in[7];
    const float* Wv       = (const float*)d_in[8];
    const float* Wo       = (const float*)d_in[9];
    const float* Wd       = (const float*)d_in[10];
    float* out            = (float*)d_out;

    static bool attr_set = false;
    if (!attr_set) {
        cudaFuncSetAttribute(proj_partials,
                             cudaFuncAttributeMaxDynamicSharedMemorySize,
                             SMEM_BYTES);
        attr_set = true;
    }

    proj_partials<<<640, 256, SMEM_BYTES>>>(cq, ck, cv, co, cm,
                                            Wq, Wk, Wv, Wo, Wd, out);
    reduce_out<<<3456, 256>>>(residual, out);
}